// round 13
// baseline (speedup 1.0000x reference)
#include <cuda_runtime.h>
#include <cuda_bf16.h>
#include <mma.h>
#include <cstdint>
using namespace nvcuda;

#define NT    256
#define ROWS  16
#define NBLK  128
#define TSEQ  256
#define FIN   64
typedef unsigned long long u64;

// weights, bf16 hi/lo, row-major [m][k] padded ld
__device__ __nv_bfloat16 g_W0h[256*72], g_W0l[256*72];   // W0^T  m=256, k=64, ld=72
__device__ __nv_bfloat16 g_A0h[256*72], g_A0l[256*72];   // U0^T  m=256, k=64, ld=72
__device__ __nv_bfloat16 g_A1Wh[128*72], g_A1Wl[128*72]; // W1^T  m=128, k=64, ld=72
__device__ __nv_bfloat16 g_A1Uh[128*40], g_A1Ul[128*40]; // U1^T  m=128, k=32, ld=40
__device__ __nv_bfloat16 g_A2Wh[64*40],  g_A2Wl[64*40];  // W2^T  m=64,  k=32, ld=40
__device__ __nv_bfloat16 g_A2Uh[64*24],  g_A2Ul[64*24];  // U2^T  m=64,  k=16, ld=24

// ---------------- fused rec smem (bytes) ----------------
#define B0R   0          // b0 replicated [256 m][16] f32 = 16384
#define ZPRE  16384      // xW0+b0 staging, 2 x [256][16] f32 = 32768
#define XR    49152      // raw x fp32, 2 x 4096
#define XS    57344      // x bf16 stage, 2 x (hi 1152el + lo 1152el) = 2 x 4608
#define BTO   66560      // 2 x 8704 bf16 (h0hi 1152el, h0lo, h1hi 640, h1lo, h2hi 384, h2lo)
#define Z0O   83968      // 256 x 24 f32
#define Z1O   108544     // 128 x 24
#define Z2O   120832     // 64 x 24
#define HFO   126976     // 16 x 16 f32
#define SMEM2 128000

__device__ __forceinline__ uint32_t smem_u32(const void* p) {
    uint32_t a;
    asm("{ .reg .u64 t; cvta.to.shared.u64 t, %1; cvt.u32.u64 %0, t; }" : "=r"(a) : "l"(p));
    return a;
}
__device__ __forceinline__ void cpasync16(uint32_t saddr, const float* g) {
    asm volatile("cp.async.ca.shared.global [%0], [%1], 16;" :: "r"(saddr), "l"(g));
}
__device__ __forceinline__ float tanhap(float x) {
    float y; asm("tanh.approx.f32 %0, %1;" : "=f"(y) : "f"(x));
    return y;
}
__device__ __forceinline__ float sigap(float x) { return fmaf(0.5f, tanhap(0.5f*x), 0.5f); }

// ========== PROLOGUE: split weights into bf16 hi/lo ==========
__global__ void wconv_kernel(const float* __restrict__ W0, const float* __restrict__ U0,
                             const float* __restrict__ W1, const float* __restrict__ U1,
                             const float* __restrict__ W2, const float* __restrict__ U2)
{
    const int t = blockIdx.x * blockDim.x + threadIdx.x;
    const int S = gridDim.x * blockDim.x;
    for (int i = t; i < 256*72; i += S) {
        int m = i / 72, k = i % 72;
        float v = (k < 64) ? W0[k*256 + m] : 0.f;
        __nv_bfloat16 h = __float2bfloat16(v);
        g_W0h[i] = h; g_W0l[i] = __float2bfloat16(v - __bfloat162float(h));
    }
    for (int i = t; i < 256*72; i += S) {
        int m = i / 72, k = i % 72;
        float v = (k < 64) ? U0[k*256 + m] : 0.f;
        __nv_bfloat16 h = __float2bfloat16(v);
        g_A0h[i] = h; g_A0l[i] = __float2bfloat16(v - __bfloat162float(h));
    }
    for (int i = t; i < 128*72; i += S) {
        int m = i / 72, k = i % 72;
        float v = (k < 64) ? W1[k*128 + m] : 0.f;
        __nv_bfloat16 h = __float2bfloat16(v);
        g_A1Wh[i] = h; g_A1Wl[i] = __float2bfloat16(v - __bfloat162float(h));
    }
    for (int i = t; i < 128*40; i += S) {
        int m = i / 40, k = i % 40;
        float v = (k < 32) ? U1[k*128 + m] : 0.f;
        __nv_bfloat16 h = __float2bfloat16(v);
        g_A1Uh[i] = h; g_A1Ul[i] = __float2bfloat16(v - __bfloat162float(h));
    }
    for (int i = t; i < 64*40; i += S) {
        int m = i / 40, k = i % 40;
        float v = (k < 32) ? W2[k*64 + m] : 0.f;
        __nv_bfloat16 h = __float2bfloat16(v);
        g_A2Wh[i] = h; g_A2Wl[i] = __float2bfloat16(v - __bfloat162float(h));
    }
    for (int i = t; i < 64*24; i += S) {
        int m = i / 24, k = i % 24;
        float v = (k < 16) ? U2[k*64 + m] : 0.f;
        __nv_bfloat16 h = __float2bfloat16(v);
        g_A2Uh[i] = h; g_A2Ul[i] = __float2bfloat16(v - __bfloat162float(h));
    }
}

typedef wmma::fragment<wmma::matrix_a, 16,16,16, __nv_bfloat16, wmma::row_major> FragA;
typedef wmma::fragment<wmma::matrix_b, 16,16,16, __nv_bfloat16, wmma::col_major> FragB;
typedef wmma::fragment<wmma::accumulator, 16,16,16, float> FragC;

// ========== FUSED recurrent kernel ==========
__global__ void __launch_bounds__(NT, 1) lstm3_fused(
    const float* __restrict__ x, const float* __restrict__ b0,
    const float* __restrict__ b1, const float* __restrict__ b2,
    const float* __restrict__ Wd, const float* __restrict__ bd,
    float* __restrict__ out)
{
    extern __shared__ char smc[];
    const int tid = threadIdx.x, wid = tid >> 5, bx = blockIdx.x;
    const int lw = wid - 4;
    const int row0 = bx * ROWS;

    float* b0rep = reinterpret_cast<float*>(smc + B0R);
    float* zpre  = reinterpret_cast<float*>(smc + ZPRE);
    for (int i = tid; i < 4096; i += NT) b0rep[i] = b0[i >> 4];
    for (int i = tid; i < 4352; i += NT) reinterpret_cast<uint32_t*>(smc + BTO)[i] = 0u;

    // cp.async x(t=0) -> XR buf0, x(t=1) -> XR buf1
    const int xrw = tid >> 4, kg = tid & 15;
    const float* xsrc = x + (size_t)(row0 + xrw)*(TSEQ*FIN) + kg*4;
    {
        uint32_t sa = smem_u32(smc + XR) + xrw*256 + kg*16;
        cpasync16(sa, xsrc);
        cpasync16(sa + 4096, xsrc + 64);
        asm volatile("cp.async.commit_group;" ::: "memory");
    }

    // resident HI fragments only (lo streamed from L1-resident global)
    FragA ah[16];
    if (wid < 4) {
#pragma unroll
        for (int i = 0; i < 4; ++i)
#pragma unroll
            for (int kk = 0; kk < 4; ++kk)
                wmma::load_matrix_sync(ah[i*4+kk], g_A0h + (wid*4+i)*16*72 + kk*16, 72);
    } else {
#pragma unroll
        for (int t2 = 0; t2 < 2; ++t2) {
            const int mt = lw*2 + t2;
#pragma unroll
            for (int kk = 0; kk < 4; ++kk)
                wmma::load_matrix_sync(ah[t2*6+kk], g_A1Wh + mt*16*72 + kk*16, 72);
#pragma unroll
            for (int u = 0; u < 2; ++u)
                wmma::load_matrix_sync(ah[t2*6+4+u], g_A1Uh + mt*16*40 + u*16, 40);
        }
#pragma unroll
        for (int kk = 0; kk < 2; ++kk)
            wmma::load_matrix_sync(ah[12+kk], g_A2Wh + lw*16*40 + kk*16, 40);
        wmma::load_matrix_sync(ah[14], g_A2Uh + lw*16*24, 24);
    }

    // epilogue roles
    const int u0e = tid & 63,  q0 = tid >> 6;
    const int u1e = tid & 31,  q1 = (tid & 127) >> 5;
    const int u2e = tid & 15,  q2 = (tid & 63) >> 4;
    float b1r[4] = {0,0,0,0}, b2r[4] = {0,0,0,0};
    if (tid < 128) { b1r[0]=b1[u1e]; b1r[1]=b1[32+u1e]; b1r[2]=b1[64+u1e]; b1r[3]=b1[96+u1e]; }
    if (tid < 64)  { b2r[0]=b2[u2e]; b2r[1]=b2[16+u2e]; b2r[2]=b2[32+u2e]; b2r[3]=b2[48+u2e]; }
    float c0[4] = {0,0,0,0}, c1[4] = {0,0,0,0}, c2[4] = {0,0,0,0};

    float* z0 = reinterpret_cast<float*>(smc + Z0O);
    float* z1 = reinterpret_cast<float*>(smc + Z1O);
    float* z2 = reinterpret_cast<float*>(smc + Z2O);
    float* hf = reinterpret_cast<float*>(smc + HFO);
    float* xraw = reinterpret_cast<float*>(smc + XR);

    // wait x(0), x(1); convert to bf16 stages (parity 0 and 1)
    asm volatile("cp.async.wait_group 0;" ::: "memory");
    __syncthreads();
#pragma unroll
    for (int pb = 0; pb < 2; ++pb) {
        float4 xv = *reinterpret_cast<const float4*>(xraw + pb*1024 + xrw*64 + kg*4);
        __nv_bfloat16* sh = reinterpret_cast<__nv_bfloat16*>(smc + XS + pb*4608);
        __nv_bfloat16* sl = sh + 1152;
        float vx[4] = {xv.x, xv.y, xv.z, xv.w};
        __nv_bfloat16 hi[4], lo[4];
#pragma unroll
        for (int j = 0; j < 4; ++j) {
            hi[j] = __float2bfloat16(vx[j]);
            lo[j] = __float2bfloat16(vx[j] - __bfloat162float(hi[j]));
        }
        *reinterpret_cast<__nv_bfloat162*>(sh + xrw*72 + kg*4)     = __nv_bfloat162(hi[0], hi[1]);
        *reinterpret_cast<__nv_bfloat162*>(sh + xrw*72 + kg*4 + 2) = __nv_bfloat162(hi[2], hi[3]);
        *reinterpret_cast<__nv_bfloat162*>(sl + xrw*72 + kg*4)     = __nv_bfloat162(lo[0], lo[1]);
        *reinterpret_cast<__nv_bfloat162*>(sl + xrw*72 + kg*4 + 2) = __nv_bfloat162(lo[2], lo[3]);
    }
    __syncthreads();

    // prologue: zpre[0] = b0 + x@W0(0)  (all 8 warps, 2 m-tiles each, from stage parity 0)
    {
        const __nv_bfloat16* sh = reinterpret_cast<const __nv_bfloat16*>(smc + XS);
        const __nv_bfloat16* sl = sh + 1152;
        FragC az[2];
#pragma unroll
        for (int i = 0; i < 2; ++i)
            wmma::load_matrix_sync(az[i], b0rep + (wid*2+i)*256, 16, wmma::mem_row_major);
        FragB xbh, xbl;
        FragA wh, wl;
#pragma unroll
        for (int kk = 0; kk < 4; ++kk) {
            wmma::load_matrix_sync(xbh, sh + kk*16, 72);
            wmma::load_matrix_sync(xbl, sl + kk*16, 72);
#pragma unroll
            for (int i = 0; i < 2; ++i) {
                wmma::load_matrix_sync(wh, g_W0h + (wid*2+i)*16*72 + kk*16, 72);
                wmma::load_matrix_sync(wl, g_W0l + (wid*2+i)*16*72 + kk*16, 72);
                wmma::mma_sync(az[i], wh, xbh, az[i]);
                wmma::mma_sync(az[i], wh, xbl, az[i]);
                wmma::mma_sync(az[i], wl, xbh, az[i]);
            }
        }
#pragma unroll
        for (int i = 0; i < 2; ++i)
            wmma::store_matrix_sync(zpre + (wid*2+i)*256, az[i], 16, wmma::mem_row_major);
    }
    __syncthreads();

    for (int s = 0; s < TSEQ + 2; ++s) {
        const int p = s & 1;

        // cp.async x(s+2) into raw parity p
        if (s + 2 < TSEQ) {
            uint32_t sa = smem_u32(smc + XR) + p*4096 + xrw*256 + kg*16;
            cpasync16(sa, xsrc + (size_t)(s+2)*64);
            asm volatile("cp.async.commit_group;" ::: "memory");
        }

        const __nv_bfloat16* br0h = reinterpret_cast<const __nv_bfloat16*>(smc + BTO + p*8704);
        const __nv_bfloat16* br0l = br0h + 1152;
        const __nv_bfloat16* br1h = br0h + 2304;
        const __nv_bfloat16* br1l = br0h + 2944;
        const __nv_bfloat16* br2h = br0h + 3584;
        const __nv_bfloat16* br2l = br0h + 3968;

        FragB bh, bl;
        FragA alv;

        if (wid < 4) {
            if (s < TSEQ) {
                // z0(s) = zpre[p] (b0 + xW0(s)) + U0·h0(s-1)
                FragC acc[4];
#pragma unroll
                for (int i = 0; i < 4; ++i)
                    wmma::load_matrix_sync(acc[i], zpre + p*4096 + (wid*4+i)*256, 16, wmma::mem_row_major);
#pragma unroll
                for (int kk = 0; kk < 4; ++kk) {
                    wmma::load_matrix_sync(bh, br0h + kk*16, 72);
                    wmma::load_matrix_sync(bl, br0l + kk*16, 72);
#pragma unroll
                    for (int i = 0; i < 4; ++i) {
                        wmma::mma_sync(acc[i], ah[i*4+kk], bh, acc[i]);
                        wmma::mma_sync(acc[i], ah[i*4+kk], bl, acc[i]);
                        wmma::load_matrix_sync(alv, g_A0l + (wid*4+i)*16*72 + kk*16, 72);
                        wmma::mma_sync(acc[i], alv, bh, acc[i]);
                    }
                }
#pragma unroll
                for (int i = 0; i < 4; ++i)
                    wmma::store_matrix_sync(z0 + (wid*4+i)*16*24, acc[i], 24, wmma::mem_row_major);
            }
        } else {
            FragC acc[3];
            if (s >= 1 && s <= TSEQ) {
                wmma::fill_fragment(acc[0], 0.0f);
                wmma::fill_fragment(acc[1], 0.0f);
#pragma unroll
                for (int kk = 0; kk < 4; ++kk) {
                    wmma::load_matrix_sync(bh, br0h + kk*16, 72);
                    wmma::load_matrix_sync(bl, br0l + kk*16, 72);
#pragma unroll
                    for (int t2 = 0; t2 < 2; ++t2) {
                        wmma::mma_sync(acc[t2], ah[t2*6+kk], bh, acc[t2]);
                        wmma::mma_sync(acc[t2], ah[t2*6+kk], bl, acc[t2]);
                        wmma::load_matrix_sync(alv, g_A1Wl + (lw*2+t2)*16*72 + kk*16, 72);
                        wmma::mma_sync(acc[t2], alv, bh, acc[t2]);
                    }
                }
#pragma unroll
                for (int u = 0; u < 2; ++u) {
                    wmma::load_matrix_sync(bh, br1h + u*16, 40);
                    wmma::load_matrix_sync(bl, br1l + u*16, 40);
#pragma unroll
                    for (int t2 = 0; t2 < 2; ++t2) {
                        wmma::mma_sync(acc[t2], ah[t2*6+4+u], bh, acc[t2]);
                        wmma::mma_sync(acc[t2], ah[t2*6+4+u], bl, acc[t2]);
                        wmma::load_matrix_sync(alv, g_A1Ul + (lw*2+t2)*16*40 + u*16, 40);
                        wmma::mma_sync(acc[t2], alv, bh, acc[t2]);
                    }
                }
#pragma unroll
                for (int t2 = 0; t2 < 2; ++t2)
                    wmma::store_matrix_sync(z1 + (lw*2+t2)*16*24, acc[t2], 24, wmma::mem_row_major);
            }
            if (s >= 2) {
                wmma::fill_fragment(acc[2], 0.0f);
#pragma unroll
                for (int kk = 0; kk < 2; ++kk) {
                    wmma::load_matrix_sync(bh, br1h + kk*16, 40);
                    wmma::load_matrix_sync(bl, br1l + kk*16, 40);
                    wmma::mma_sync(acc[2], ah[12+kk], bh, acc[2]);
                    wmma::mma_sync(acc[2], ah[12+kk], bl, acc[2]);
                    wmma::load_matrix_sync(alv, g_A2Wl + lw*16*40 + kk*16, 40);
                    wmma::mma_sync(acc[2], alv, bh, acc[2]);
                }
                wmma::load_matrix_sync(bh, br2h, 24);
                wmma::load_matrix_sync(bl, br2l, 24);
                wmma::mma_sync(acc[2], ah[14], bh, acc[2]);
                wmma::mma_sync(acc[2], ah[14], bl, acc[2]);
                wmma::load_matrix_sync(alv, g_A2Ul + lw*16*24, 24);
                wmma::mma_sync(acc[2], alv, bh, acc[2]);
                wmma::store_matrix_sync(z2 + lw*16*24, acc[2], 24, wmma::mem_row_major);
            }
        }

        // xW0(s+1) -> zpre[p^1]  (ALL warps, 2 m-tiles each; independent work)
        if (s + 1 < TSEQ) {
            const __nv_bfloat16* sh = reinterpret_cast<const __nv_bfloat16*>(smc + XS + ((s+1)&1)*4608);
            const __nv_bfloat16* sl = sh + 1152;
            float* zpw = zpre + (p^1)*4096;
            FragC az[2];
#pragma unroll
            for (int i = 0; i < 2; ++i)
                wmma::load_matrix_sync(az[i], b0rep + (wid*2+i)*256, 16, wmma::mem_row_major);
            FragB xbh, xbl;
            FragA wh, wl;
#pragma unroll
            for (int kk = 0; kk < 4; ++kk) {
                wmma::load_matrix_sync(xbh, sh + kk*16, 72);
                wmma::load_matrix_sync(xbl, sl + kk*16, 72);
#pragma unroll
                for (int i = 0; i < 2; ++i) {
                    wmma::load_matrix_sync(wh, g_W0h + (wid*2+i)*16*72 + kk*16, 72);
                    wmma::load_matrix_sync(wl, g_W0l + (wid*2+i)*16*72 + kk*16, 72);
                    wmma::mma_sync(az[i], wh, xbh, az[i]);
                    wmma::mma_sync(az[i], wh, xbl, az[i]);
                    wmma::mma_sync(az[i], wl, xbh, az[i]);
                }
            }
#pragma unroll
            for (int i = 0; i < 2; ++i)
                wmma::store_matrix_sync(zpw + (wid*2+i)*256, az[i], 16, wmma::mem_row_major);
        }
        __syncthreads();   // z + zpre published; B(p)/xstage reads complete

        __nv_bfloat16* bw0h = reinterpret_cast<__nv_bfloat16*>(smc + BTO + (p^1)*8704);
        __nv_bfloat16* bw0l = bw0h + 1152;
        __nv_bfloat16* bw1h = bw0h + 2304;
        __nv_bfloat16* bw1l = bw0h + 2944;
        __nv_bfloat16* bw2h = bw0h + 3584;
        __nv_bfloat16* bw2l = bw0h + 3968;

        if (s < TSEQ) {   // L0 epilogue (b0 already inside z0 via zpre)
            float4 zi = *reinterpret_cast<const float4*>(z0 + (u0e      )*24 + 4*q0);
            float4 zf = *reinterpret_cast<const float4*>(z0 + (64 + u0e )*24 + 4*q0);
            float4 zg = *reinterpret_cast<const float4*>(z0 + (128 + u0e)*24 + 4*q0);
            float4 zo = *reinterpret_cast<const float4*>(z0 + (192 + u0e)*24 + 4*q0);
            float iv[4] = {zi.x,zi.y,zi.z,zi.w}, fv[4] = {zf.x,zf.y,zf.z,zf.w};
            float gv[4] = {zg.x,zg.y,zg.z,zg.w}, ov[4] = {zo.x,zo.y,zo.z,zo.w};
#pragma unroll
            for (int j = 0; j < 4; ++j) {
                float ig = sigap(iv[j]), fg = sigap(fv[j]);
                float gg = tanhap(gv[j]), og = sigap(ov[j]);
                c0[j] = fg * c0[j] + ig * gg;
                float h = og * tanhap(c0[j]);
                int n = 4*q0 + j;
                __nv_bfloat16 hi = __float2bfloat16(h);
                bw0h[n*72 + u0e] = hi;
                bw0l[n*72 + u0e] = __float2bfloat16(h - __bfloat162float(hi));
            }
        }
        if (s >= 1 && s <= TSEQ && tid < 128) {   // L1 epilogue
            float4 zi = *reinterpret_cast<const float4*>(z1 + (u1e     )*24 + 4*q1);
            float4 zf = *reinterpret_cast<const float4*>(z1 + (32 + u1e)*24 + 4*q1);
            float4 zg = *reinterpret_cast<const float4*>(z1 + (64 + u1e)*24 + 4*q1);
            float4 zo = *reinterpret_cast<const float4*>(z1 + (96 + u1e)*24 + 4*q1);
            float iv[4] = {zi.x,zi.y,zi.z,zi.w}, fv[4] = {zf.x,zf.y,zf.z,zf.w};
            float gv[4] = {zg.x,zg.y,zg.z,zg.w}, ov[4] = {zo.x,zo.y,zo.z,zo.w};
#pragma unroll
            for (int j = 0; j < 4; ++j) {
                float ig = sigap(iv[j] + b1r[0]), fg = sigap(fv[j] + b1r[1]);
                float gg = tanhap(gv[j] + b1r[2]), og = sigap(ov[j] + b1r[3]);
                c1[j] = fg * c1[j] + ig * gg;
                float h = og * tanhap(c1[j]);
                int n = 4*q1 + j;
                __nv_bfloat16 hi = __float2bfloat16(h);
                bw1h[n*40 + u1e] = hi;
                bw1l[n*40 + u1e] = __float2bfloat16(h - __bfloat162float(hi));
            }
        }
        if (s >= 2 && tid < 64) {   // L2 epilogue
            float4 zi = *reinterpret_cast<const float4*>(z2 + (u2e     )*24 + 4*q2);
            float4 zf = *reinterpret_cast<const float4*>(z2 + (16 + u2e)*24 + 4*q2);
            float4 zg = *reinterpret_cast<const float4*>(z2 + (32 + u2e)*24 + 4*q2);
            float4 zo = *reinterpret_cast<const float4*>(z2 + (48 + u2e)*24 + 4*q2);
            float iv[4] = {zi.x,zi.y,zi.z,zi.w}, fv[4] = {zf.x,zf.y,zf.z,zf.w};
            float gv[4] = {zg.x,zg.y,zg.z,zg.w}, ov[4] = {zo.x,zo.y,zo.z,zo.w};
#pragma unroll
            for (int j = 0; j < 4; ++j) {
                float ig = sigap(iv[j] + b2r[0]), fg = sigap(fv[j] + b2r[1]);
                float gg = tanhap(gv[j] + b2r[2]), og = sigap(ov[j] + b2r[3]);
                c2[j] = fg * c2[j] + ig * gg;
                float h = og * tanhap(c2[j]);
                int n = 4*q2 + j;
                __nv_bfloat16 hi = __float2bfloat16(h);
                bw2h[n*24 + u2e] = hi;
                bw2l[n*24 + u2e] = __float2bfloat16(h - __bfloat162float(hi));
                if (s == TSEQ + 1) hf[n*16 + u2e] = h;
            }
        }

        // convert x(s+2) raw -> bf16 stage parity p
        if (s + 2 < TSEQ) {
            asm volatile("cp.async.wait_group 0;" ::: "memory");
            float4 xv = *reinterpret_cast<const float4*>(xraw + p*1024 + xrw*64 + kg*4);
            __nv_bfloat16* sh = reinterpret_cast<__nv_bfloat16*>(smc + XS + p*4608);
            __nv_bfloat16* sl = sh + 1152;
            float vx[4] = {xv.x, xv.y, xv.z, xv.w};
            __nv_bfloat16 hi[4], lo[4];
#pragma unroll
            for (int j = 0; j < 4; ++j) {
                hi[j] = __float2bfloat16(vx[j]);
                lo[j] = __float2bfloat16(vx[j] - __bfloat162float(hi[j]));
            }
            *reinterpret_cast<__nv_bfloat162*>(sh + xrw*72 + kg*4)     = __nv_bfloat162(hi[0], hi[1]);
            *reinterpret_cast<__nv_bfloat162*>(sh + xrw*72 + kg*4 + 2) = __nv_bfloat162(hi[2], hi[3]);
            *reinterpret_cast<__nv_bfloat162*>(sl + xrw*72 + kg*4)     = __nv_bfloat162(lo[0], lo[1]);
            *reinterpret_cast<__nv_bfloat162*>(sl + xrw*72 + kg*4 + 2) = __nv_bfloat162(lo[2], lo[3]);
        }
        __syncthreads();   // h(p^1) + xstage published
    }

    // ---- Dense head ----
    if (tid < 16) {
        float a = bd[0];
#pragma unroll
        for (int u = 0; u < 16; ++u) a += hf[tid*16 + u] * Wd[u];
        out[bx*ROWS + tid] = a;
    }
}

extern "C" void kernel_launch(void* const* d_in, const int* in_sizes, int n_in,
                              void* d_out, int out_size)
{
    (void)in_sizes; (void)n_in; (void)out_size;
    const float* x  = (const float*)d_in[0];
    const float* W0 = (const float*)d_in[1];
    const float* U0 = (const float*)d_in[2];
    const float* b0 = (const float*)d_in[3];
    const float* W1 = (const float*)d_in[4];
    const float* U1 = (const float*)d_in[5];
    const float* b1 = (const float*)d_in[6];
    const float* W2 = (const float*)d_in[7];
    const float* U2 = (const float*)d_in[8];
    const float* b2 = (const float*)d_in[9];
    const float* Wd = (const float*)d_in[10];
    const float* bd = (const float*)d_in[11];
    float* out = (float*)d_out;

    cudaFuncSetAttribute(lstm3_fused, cudaFuncAttributeMaxDynamicSharedMemorySize, SMEM2);

    wconv_kernel<<<32, 256>>>(W0, U0, W1, U1, W2, U2);
    lstm3_fused<<<NBLK, NT, SMEM2>>>(x, b0, b1, b2, Wd, bd, out);
}

// round 14
// speedup vs baseline: 1.4914x; 1.4914x over previous
#include <cuda_runtime.h>
#include <cuda_bf16.h>
#include <mma.h>
#include <cstdint>
using namespace nvcuda;

#define NT    256
#define ROWS  16
#define NBLK  128
#define TSEQ  256
#define FIN   64
typedef unsigned long long u64;

// weights, bf16 hi/lo, row-major [m][k] padded ld
__device__ __nv_bfloat16 g_W0h[256*72], g_W0l[256*72];   // W0^T  m=256, k=64, ld=72
__device__ __nv_bfloat16 g_A0h[256*72], g_A0l[256*72];   // U0^T  m=256, k=64, ld=72
__device__ __nv_bfloat16 g_A1Wh[128*72], g_A1Wl[128*72]; // W1^T  m=128, k=64, ld=72
__device__ __nv_bfloat16 g_A1Uh[128*40], g_A1Ul[128*40]; // U1^T  m=128, k=32, ld=40
__device__ __nv_bfloat16 g_A2Wh[64*40],  g_A2Wl[64*40];  // W2^T  m=64,  k=32, ld=40
__device__ __nv_bfloat16 g_A2Uh[64*24],  g_A2Ul[64*24];  // U2^T  m=64,  k=16, ld=24

// ---------------- fused rec smem (bytes) ----------------
#define B0R   0          // b0 replicated [256 m][16] f32 = 16384
#define ZPRE  16384      // xW0+b0 staging, 2 x [256][16] f32 = 32768
#define XR    49152      // raw x fp32, 2 x 4096
#define XS    57344      // x bf16 stage, 2 x (hi 1152el + lo 1152el) = 2 x 4608
#define BTO   66560      // 2 x 8704 bf16 (h0hi 1152el, h0lo, h1hi 640, h1lo, h2hi 384, h2lo)
#define Z0O   83968      // 256 x 24 f32
#define Z1O   108544     // 128 x 24
#define Z2O   120832     // 64 x 24
#define HFO   126976     // 16 x 16 f32
#define W0S   128000     // W0 bf16 hi (18432 el) + lo (18432 el) = 73728
#define SMEM2 201728

__device__ __forceinline__ uint32_t smem_u32(const void* p) {
    uint32_t a;
    asm("{ .reg .u64 t; cvta.to.shared.u64 t, %1; cvt.u32.u64 %0, t; }" : "=r"(a) : "l"(p));
    return a;
}
__device__ __forceinline__ void cpasync16(uint32_t saddr, const float* g) {
    asm volatile("cp.async.ca.shared.global [%0], [%1], 16;" :: "r"(saddr), "l"(g));
}
__device__ __forceinline__ float tanhap(float x) {
    float y; asm("tanh.approx.f32 %0, %1;" : "=f"(y) : "f"(x));
    return y;
}
__device__ __forceinline__ float sigap(float x) { return fmaf(0.5f, tanhap(0.5f*x), 0.5f); }

// ========== PROLOGUE: split weights into bf16 hi/lo ==========
__global__ void wconv_kernel(const float* __restrict__ W0, const float* __restrict__ U0,
                             const float* __restrict__ W1, const float* __restrict__ U1,
                             const float* __restrict__ W2, const float* __restrict__ U2)
{
    const int t = blockIdx.x * blockDim.x + threadIdx.x;
    const int S = gridDim.x * blockDim.x;
    for (int i = t; i < 256*72; i += S) {
        int m = i / 72, k = i % 72;
        float v = (k < 64) ? W0[k*256 + m] : 0.f;
        __nv_bfloat16 h = __float2bfloat16(v);
        g_W0h[i] = h; g_W0l[i] = __float2bfloat16(v - __bfloat162float(h));
    }
    for (int i = t; i < 256*72; i += S) {
        int m = i / 72, k = i % 72;
        float v = (k < 64) ? U0[k*256 + m] : 0.f;
        __nv_bfloat16 h = __float2bfloat16(v);
        g_A0h[i] = h; g_A0l[i] = __float2bfloat16(v - __bfloat162float(h));
    }
    for (int i = t; i < 128*72; i += S) {
        int m = i / 72, k = i % 72;
        float v = (k < 64) ? W1[k*128 + m] : 0.f;
        __nv_bfloat16 h = __float2bfloat16(v);
        g_A1Wh[i] = h; g_A1Wl[i] = __float2bfloat16(v - __bfloat162float(h));
    }
    for (int i = t; i < 128*40; i += S) {
        int m = i / 40, k = i % 40;
        float v = (k < 32) ? U1[k*128 + m] : 0.f;
        __nv_bfloat16 h = __float2bfloat16(v);
        g_A1Uh[i] = h; g_A1Ul[i] = __float2bfloat16(v - __bfloat162float(h));
    }
    for (int i = t; i < 64*40; i += S) {
        int m = i / 40, k = i % 40;
        float v = (k < 32) ? W2[k*64 + m] : 0.f;
        __nv_bfloat16 h = __float2bfloat16(v);
        g_A2Wh[i] = h; g_A2Wl[i] = __float2bfloat16(v - __bfloat162float(h));
    }
    for (int i = t; i < 64*24; i += S) {
        int m = i / 24, k = i % 24;
        float v = (k < 16) ? U2[k*64 + m] : 0.f;
        __nv_bfloat16 h = __float2bfloat16(v);
        g_A2Uh[i] = h; g_A2Ul[i] = __float2bfloat16(v - __bfloat162float(h));
    }
}

typedef wmma::fragment<wmma::matrix_a, 16,16,16, __nv_bfloat16, wmma::row_major> FragA;
typedef wmma::fragment<wmma::matrix_b, 16,16,16, __nv_bfloat16, wmma::col_major> FragB;
typedef wmma::fragment<wmma::accumulator, 16,16,16, float> FragC;

// ========== FUSED recurrent kernel ==========
__global__ void __launch_bounds__(NT, 1) lstm3_fused(
    const float* __restrict__ x, const float* __restrict__ b0,
    const float* __restrict__ b1, const float* __restrict__ b2,
    const float* __restrict__ Wd, const float* __restrict__ bd,
    float* __restrict__ out)
{
    extern __shared__ char smc[];
    const int tid = threadIdx.x, wid = tid >> 5, bx = blockIdx.x;
    const int lw = wid - 4;
    const int row0 = bx * ROWS;

    float* b0rep = reinterpret_cast<float*>(smc + B0R);
    float* zpre  = reinterpret_cast<float*>(smc + ZPRE);
    __nv_bfloat16* w0sh = reinterpret_cast<__nv_bfloat16*>(smc + W0S);
    __nv_bfloat16* w0sl = w0sh + 18432;
    for (int i = tid; i < 4096; i += NT) b0rep[i] = b0[i >> 4];
    for (int i = tid; i < 4352; i += NT) reinterpret_cast<uint32_t*>(smc + BTO)[i] = 0u;
    // copy W0 hi/lo into smem (vectorized 8 bf16 at a time)
    for (int i = tid*8; i < 18432; i += NT*8) {
        *reinterpret_cast<uint4*>(w0sh + i) = *reinterpret_cast<const uint4*>(g_W0h + i);
        *reinterpret_cast<uint4*>(w0sl + i) = *reinterpret_cast<const uint4*>(g_W0l + i);
    }

    // cp.async x(t=0) -> XR buf0, x(t=1) -> XR buf1
    const int xrw = tid >> 4, kg = tid & 15;
    const float* xsrc = x + (size_t)(row0 + xrw)*(TSEQ*FIN) + kg*4;
    {
        uint32_t sa = smem_u32(smc + XR) + xrw*256 + kg*16;
        cpasync16(sa, xsrc);
        cpasync16(sa + 4096, xsrc + 64);
        asm volatile("cp.async.commit_group;" ::: "memory");
    }

    // resident hi+lo fragments for U0 / L1 / L2
    FragA ah[16], al[16];
    if (wid < 4) {
#pragma unroll
        for (int i = 0; i < 4; ++i)
#pragma unroll
            for (int kk = 0; kk < 4; ++kk) {
                wmma::load_matrix_sync(ah[i*4+kk], g_A0h + (wid*4+i)*16*72 + kk*16, 72);
                wmma::load_matrix_sync(al[i*4+kk], g_A0l + (wid*4+i)*16*72 + kk*16, 72);
            }
    } else {
#pragma unroll
        for (int t2 = 0; t2 < 2; ++t2) {
            const int mt = lw*2 + t2;
#pragma unroll
            for (int kk = 0; kk < 4; ++kk) {
                wmma::load_matrix_sync(ah[t2*6+kk], g_A1Wh + mt*16*72 + kk*16, 72);
                wmma::load_matrix_sync(al[t2*6+kk], g_A1Wl + mt*16*72 + kk*16, 72);
            }
#pragma unroll
            for (int u = 0; u < 2; ++u) {
                wmma::load_matrix_sync(ah[t2*6+4+u], g_A1Uh + mt*16*40 + u*16, 40);
                wmma::load_matrix_sync(al[t2*6+4+u], g_A1Ul + mt*16*40 + u*16, 40);
            }
        }
#pragma unroll
        for (int kk = 0; kk < 2; ++kk) {
            wmma::load_matrix_sync(ah[12+kk], g_A2Wh + lw*16*40 + kk*16, 40);
            wmma::load_matrix_sync(al[12+kk], g_A2Wl + lw*16*40 + kk*16, 40);
        }
        wmma::load_matrix_sync(ah[14], g_A2Uh + lw*16*24, 24);
        wmma::load_matrix_sync(al[14], g_A2Ul + lw*16*24, 24);
    }

    // epilogue roles
    const int u0e = tid & 63,  q0 = tid >> 6;
    const int u1e = tid & 31,  q1 = (tid & 127) >> 5;
    const int u2e = tid & 15,  q2 = (tid & 63) >> 4;
    float b1r[4] = {0,0,0,0}, b2r[4] = {0,0,0,0};
    if (tid < 128) { b1r[0]=b1[u1e]; b1r[1]=b1[32+u1e]; b1r[2]=b1[64+u1e]; b1r[3]=b1[96+u1e]; }
    if (tid < 64)  { b2r[0]=b2[u2e]; b2r[1]=b2[16+u2e]; b2r[2]=b2[32+u2e]; b2r[3]=b2[48+u2e]; }
    float c0[4] = {0,0,0,0}, c1[4] = {0,0,0,0}, c2[4] = {0,0,0,0};

    float* z0 = reinterpret_cast<float*>(smc + Z0O);
    float* z1 = reinterpret_cast<float*>(smc + Z1O);
    float* z2 = reinterpret_cast<float*>(smc + Z2O);
    float* hf = reinterpret_cast<float*>(smc + HFO);
    float* xraw = reinterpret_cast<float*>(smc + XR);

    // wait x(0), x(1); convert to bf16 stages (parity 0 and 1)
    asm volatile("cp.async.wait_group 0;" ::: "memory");
    __syncthreads();   // xraw + b0rep + W0 smem ready
#pragma unroll
    for (int pb = 0; pb < 2; ++pb) {
        float4 xv = *reinterpret_cast<const float4*>(xraw + pb*1024 + xrw*64 + kg*4);
        __nv_bfloat16* sh = reinterpret_cast<__nv_bfloat16*>(smc + XS + pb*4608);
        __nv_bfloat16* sl = sh + 1152;
        float vx[4] = {xv.x, xv.y, xv.z, xv.w};
        __nv_bfloat16 hi[4], lo[4];
#pragma unroll
        for (int j = 0; j < 4; ++j) {
            hi[j] = __float2bfloat16(vx[j]);
            lo[j] = __float2bfloat16(vx[j] - __bfloat162float(hi[j]));
        }
        *reinterpret_cast<__nv_bfloat162*>(sh + xrw*72 + kg*4)     = __nv_bfloat162(hi[0], hi[1]);
        *reinterpret_cast<__nv_bfloat162*>(sh + xrw*72 + kg*4 + 2) = __nv_bfloat162(hi[2], hi[3]);
        *reinterpret_cast<__nv_bfloat162*>(sl + xrw*72 + kg*4)     = __nv_bfloat162(lo[0], lo[1]);
        *reinterpret_cast<__nv_bfloat162*>(sl + xrw*72 + kg*4 + 2) = __nv_bfloat162(lo[2], lo[3]);
    }
    __syncthreads();

    // prologue: zpre[0] = b0 + x@W0(0)  (all 8 warps, 2 m-tiles each)
    {
        const __nv_bfloat16* sh = reinterpret_cast<const __nv_bfloat16*>(smc + XS);
        const __nv_bfloat16* sl = sh + 1152;
        FragC az[2];
#pragma unroll
        for (int i = 0; i < 2; ++i)
            wmma::load_matrix_sync(az[i], b0rep + (wid*2+i)*256, 16, wmma::mem_row_major);
        FragB xbh, xbl;
        FragA wh, wl;
#pragma unroll
        for (int kk = 0; kk < 4; ++kk) {
            wmma::load_matrix_sync(xbh, sh + kk*16, 72);
            wmma::load_matrix_sync(xbl, sl + kk*16, 72);
#pragma unroll
            for (int i = 0; i < 2; ++i) {
                wmma::load_matrix_sync(wh, w0sh + (wid*2+i)*16*72 + kk*16, 72);
                wmma::load_matrix_sync(wl, w0sl + (wid*2+i)*16*72 + kk*16, 72);
                wmma::mma_sync(az[i], wh, xbh, az[i]);
                wmma::mma_sync(az[i], wh, xbl, az[i]);
                wmma::mma_sync(az[i], wl, xbh, az[i]);
            }
        }
#pragma unroll
        for (int i = 0; i < 2; ++i)
            wmma::store_matrix_sync(zpre + (wid*2+i)*256, az[i], 16, wmma::mem_row_major);
    }
    __syncthreads();

    for (int s = 0; s < TSEQ + 2; ++s) {
        const int p = s & 1;

        // cp.async x(s+2) into raw parity p
        if (s + 2 < TSEQ) {
            uint32_t sa = smem_u32(smc + XR) + p*4096 + xrw*256 + kg*16;
            cpasync16(sa, xsrc + (size_t)(s+2)*64);
            asm volatile("cp.async.commit_group;" ::: "memory");
        }

        const __nv_bfloat16* br0h = reinterpret_cast<const __nv_bfloat16*>(smc + BTO + p*8704);
        const __nv_bfloat16* br0l = br0h + 1152;
        const __nv_bfloat16* br1h = br0h + 2304;
        const __nv_bfloat16* br1l = br0h + 2944;
        const __nv_bfloat16* br2h = br0h + 3584;
        const __nv_bfloat16* br2l = br0h + 3968;

        FragB bh, bl;

        if (wid < 4) {
            if (s < TSEQ) {
                // z0(s) = zpre[p] (b0 + xW0(s)) + U0·h0(s-1)
                FragC acc[4];
#pragma unroll
                for (int i = 0; i < 4; ++i)
                    wmma::load_matrix_sync(acc[i], zpre + p*4096 + (wid*4+i)*256, 16, wmma::mem_row_major);
#pragma unroll
                for (int kk = 0; kk < 4; ++kk) {
                    wmma::load_matrix_sync(bh, br0h + kk*16, 72);
                    wmma::load_matrix_sync(bl, br0l + kk*16, 72);
#pragma unroll
                    for (int i = 0; i < 4; ++i) {
                        wmma::mma_sync(acc[i], ah[i*4+kk], bh, acc[i]);
                        wmma::mma_sync(acc[i], ah[i*4+kk], bl, acc[i]);
                        wmma::mma_sync(acc[i], al[i*4+kk], bh, acc[i]);
                    }
                }
#pragma unroll
                for (int i = 0; i < 4; ++i)
                    wmma::store_matrix_sync(z0 + (wid*4+i)*16*24, acc[i], 24, wmma::mem_row_major);
            }
        } else {
            FragC acc[3];
            if (s >= 1 && s <= TSEQ) {
                wmma::fill_fragment(acc[0], 0.0f);
                wmma::fill_fragment(acc[1], 0.0f);
#pragma unroll
                for (int kk = 0; kk < 4; ++kk) {
                    wmma::load_matrix_sync(bh, br0h + kk*16, 72);
                    wmma::load_matrix_sync(bl, br0l + kk*16, 72);
#pragma unroll
                    for (int t2 = 0; t2 < 2; ++t2) {
                        wmma::mma_sync(acc[t2], ah[t2*6+kk], bh, acc[t2]);
                        wmma::mma_sync(acc[t2], ah[t2*6+kk], bl, acc[t2]);
                        wmma::mma_sync(acc[t2], al[t2*6+kk], bh, acc[t2]);
                    }
                }
#pragma unroll
                for (int u = 0; u < 2; ++u) {
                    wmma::load_matrix_sync(bh, br1h + u*16, 40);
                    wmma::load_matrix_sync(bl, br1l + u*16, 40);
#pragma unroll
                    for (int t2 = 0; t2 < 2; ++t2) {
                        wmma::mma_sync(acc[t2], ah[t2*6+4+u], bh, acc[t2]);
                        wmma::mma_sync(acc[t2], ah[t2*6+4+u], bl, acc[t2]);
                        wmma::mma_sync(acc[t2], al[t2*6+4+u], bh, acc[t2]);
                    }
                }
#pragma unroll
                for (int t2 = 0; t2 < 2; ++t2)
                    wmma::store_matrix_sync(z1 + (lw*2+t2)*16*24, acc[t2], 24, wmma::mem_row_major);
            }
            if (s >= 2) {
                wmma::fill_fragment(acc[2], 0.0f);
#pragma unroll
                for (int kk = 0; kk < 2; ++kk) {
                    wmma::load_matrix_sync(bh, br1h + kk*16, 40);
                    wmma::load_matrix_sync(bl, br1l + kk*16, 40);
                    wmma::mma_sync(acc[2], ah[12+kk], bh, acc[2]);
                    wmma::mma_sync(acc[2], ah[12+kk], bl, acc[2]);
                    wmma::mma_sync(acc[2], al[12+kk], bh, acc[2]);
                }
                wmma::load_matrix_sync(bh, br2h, 24);
                wmma::load_matrix_sync(bl, br2l, 24);
                wmma::mma_sync(acc[2], ah[14], bh, acc[2]);
                wmma::mma_sync(acc[2], ah[14], bl, acc[2]);
                wmma::mma_sync(acc[2], al[14], bh, acc[2]);
                wmma::store_matrix_sync(z2 + lw*16*24, acc[2], 24, wmma::mem_row_major);
            }
        }

        // xW0(s+1) -> zpre[p^1]  (ALL warps, 2 m-tiles each; W0 from smem)
        if (s + 1 < TSEQ) {
            const __nv_bfloat16* sh = reinterpret_cast<const __nv_bfloat16*>(smc + XS + ((s+1)&1)*4608);
            const __nv_bfloat16* sl = sh + 1152;
            float* zpw = zpre + (p^1)*4096;
            FragC az[2];
#pragma unroll
            for (int i = 0; i < 2; ++i)
                wmma::load_matrix_sync(az[i], b0rep + (wid*2+i)*256, 16, wmma::mem_row_major);
            FragB xbh, xbl;
            FragA wh, wl;
#pragma unroll
            for (int kk = 0; kk < 4; ++kk) {
                wmma::load_matrix_sync(xbh, sh + kk*16, 72);
                wmma::load_matrix_sync(xbl, sl + kk*16, 72);
#pragma unroll
                for (int i = 0; i < 2; ++i) {
                    wmma::load_matrix_sync(wh, w0sh + (wid*2+i)*16*72 + kk*16, 72);
                    wmma::load_matrix_sync(wl, w0sl + (wid*2+i)*16*72 + kk*16, 72);
                    wmma::mma_sync(az[i], wh, xbh, az[i]);
                    wmma::mma_sync(az[i], wh, xbl, az[i]);
                    wmma::mma_sync(az[i], wl, xbh, az[i]);
                }
            }
#pragma unroll
            for (int i = 0; i < 2; ++i)
                wmma::store_matrix_sync(zpw + (wid*2+i)*256, az[i], 16, wmma::mem_row_major);
        }
        __syncthreads();   // z + zpre published; B(p)/xstage reads complete

        __nv_bfloat16* bw0h = reinterpret_cast<__nv_bfloat16*>(smc + BTO + (p^1)*8704);
        __nv_bfloat16* bw0l = bw0h + 1152;
        __nv_bfloat16* bw1h = bw0h + 2304;
        __nv_bfloat16* bw1l = bw0h + 2944;
        __nv_bfloat16* bw2h = bw0h + 3584;
        __nv_bfloat16* bw2l = bw0h + 3968;

        if (s < TSEQ) {   // L0 epilogue
            float4 zi = *reinterpret_cast<const float4*>(z0 + (u0e      )*24 + 4*q0);
            float4 zf = *reinterpret_cast<const float4*>(z0 + (64 + u0e )*24 + 4*q0);
            float4 zg = *reinterpret_cast<const float4*>(z0 + (128 + u0e)*24 + 4*q0);
            float4 zo = *reinterpret_cast<const float4*>(z0 + (192 + u0e)*24 + 4*q0);
            float iv[4] = {zi.x,zi.y,zi.z,zi.w}, fv[4] = {zf.x,zf.y,zf.z,zf.w};
            float gv[4] = {zg.x,zg.y,zg.z,zg.w}, ov[4] = {zo.x,zo.y,zo.z,zo.w};
#pragma unroll
            for (int j = 0; j < 4; ++j) {
                float ig = sigap(iv[j]), fg = sigap(fv[j]);
                float gg = tanhap(gv[j]), og = sigap(ov[j]);
                c0[j] = fg * c0[j] + ig * gg;
                float h = og * tanhap(c0[j]);
                int n = 4*q0 + j;
                __nv_bfloat16 hi = __float2bfloat16(h);
                bw0h[n*72 + u0e] = hi;
                bw0l[n*72 + u0e] = __float2bfloat16(h - __bfloat162float(hi));
            }
        }
        if (s >= 1 && s <= TSEQ && tid < 128) {   // L1 epilogue
            float4 zi = *reinterpret_cast<const float4*>(z1 + (u1e     )*24 + 4*q1);
            float4 zf = *reinterpret_cast<const float4*>(z1 + (32 + u1e)*24 + 4*q1);
            float4 zg = *reinterpret_cast<const float4*>(z1 + (64 + u1e)*24 + 4*q1);
            float4 zo = *reinterpret_cast<const float4*>(z1 + (96 + u1e)*24 + 4*q1);
            float iv[4] = {zi.x,zi.y,zi.z,zi.w}, fv[4] = {zf.x,zf.y,zf.z,zf.w};
            float gv[4] = {zg.x,zg.y,zg.z,zg.w}, ov[4] = {zo.x,zo.y,zo.z,zo.w};
#pragma unroll
            for (int j = 0; j < 4; ++j) {
                float ig = sigap(iv[j] + b1r[0]), fg = sigap(fv[j] + b1r[1]);
                float gg = tanhap(gv[j] + b1r[2]), og = sigap(ov[j] + b1r[3]);
                c1[j] = fg * c1[j] + ig * gg;
                float h = og * tanhap(c1[j]);
                int n = 4*q1 + j;
                __nv_bfloat16 hi = __float2bfloat16(h);
                bw1h[n*40 + u1e] = hi;
                bw1l[n*40 + u1e] = __float2bfloat16(h - __bfloat162float(hi));
            }
        }
        if (s >= 2 && tid < 64) {   // L2 epilogue
            float4 zi = *reinterpret_cast<const float4*>(z2 + (u2e     )*24 + 4*q2);
            float4 zf = *reinterpret_cast<const float4*>(z2 + (16 + u2e)*24 + 4*q2);
            float4 zg = *reinterpret_cast<const float4*>(z2 + (32 + u2e)*24 + 4*q2);
            float4 zo = *reinterpret_cast<const float4*>(z2 + (48 + u2e)*24 + 4*q2);
            float iv[4] = {zi.x,zi.y,zi.z,zi.w}, fv[4] = {zf.x,zf.y,zf.z,zf.w};
            float gv[4] = {zg.x,zg.y,zg.z,zg.w}, ov[4] = {zo.x,zo.y,zo.z,zo.w};
#pragma unroll
            for (int j = 0; j < 4; ++j) {
                float ig = sigap(iv[j] + b2r[0]), fg = sigap(fv[j] + b2r[1]);
                float gg = tanhap(gv[j] + b2r[2]), og = sigap(ov[j] + b2r[3]);
                c2[j] = fg * c2[j] + ig * gg;
                float h = og * tanhap(c2[j]);
                int n = 4*q2 + j;
                __nv_bfloat16 hi = __float2bfloat16(h);
                bw2h[n*24 + u2e] = hi;
                bw2l[n*24 + u2e] = __float2bfloat16(h - __bfloat162float(hi));
                if (s == TSEQ + 1) hf[n*16 + u2e] = h;
            }
        }

        // convert x(s+2) raw -> bf16 stage parity p
        if (s + 2 < TSEQ) {
            asm volatile("cp.async.wait_group 0;" ::: "memory");
            float4 xv = *reinterpret_cast<const float4*>(xraw + p*1024 + xrw*64 + kg*4);
            __nv_bfloat16* sh = reinterpret_cast<__nv_bfloat16*>(smc + XS + p*4608);
            __nv_bfloat16* sl = sh + 1152;
            float vx[4] = {xv.x, xv.y, xv.z, xv.w};
            __nv_bfloat16 hi[4], lo[4];
#pragma unroll
            for (int j = 0; j < 4; ++j) {
                hi[j] = __float2bfloat16(vx[j]);
                lo[j] = __float2bfloat16(vx[j] - __bfloat162float(hi[j]));
            }
            *reinterpret_cast<__nv_bfloat162*>(sh + xrw*72 + kg*4)     = __nv_bfloat162(hi[0], hi[1]);
            *reinterpret_cast<__nv_bfloat162*>(sh + xrw*72 + kg*4 + 2) = __nv_bfloat162(hi[2], hi[3]);
            *reinterpret_cast<__nv_bfloat162*>(sl + xrw*72 + kg*4)     = __nv_bfloat162(lo[0], lo[1]);
            *reinterpret_cast<__nv_bfloat162*>(sl + xrw*72 + kg*4 + 2) = __nv_bfloat162(lo[2], lo[3]);
        }
        __syncthreads();   // h(p^1) + xstage published
    }

    // ---- Dense head ----
    if (tid < 16) {
        float a = bd[0];
#pragma unroll
        for (int u = 0; u < 16; ++u) a += hf[tid*16 + u] * Wd[u];
        out[bx*ROWS + tid] = a;
    }
}

extern "C" void kernel_launch(void* const* d_in, const int* in_sizes, int n_in,
                              void* d_out, int out_size)
{
    (void)in_sizes; (void)n_in; (void)out_size;
    const float* x  = (const float*)d_in[0];
    const float* W0 = (const float*)d_in[1];
    const float* U0 = (const float*)d_in[2];
    const float* b0 = (const float*)d_in[3];
    const float* W1 = (const float*)d_in[4];
    const float* U1 = (const float*)d_in[5];
    const float* b1 = (const float*)d_in[6];
    const float* W2 = (const float*)d_in[7];
    const float* U2 = (const float*)d_in[8];
    const float* b2 = (const float*)d_in[9];
    const float* Wd = (const float*)d_in[10];
    const float* bd = (const float*)d_in[11];
    float* out = (float*)d_out;

    cudaFuncSetAttribute(lstm3_fused, cudaFuncAttributeMaxDynamicSharedMemorySize, SMEM2);

    wconv_kernel<<<32, 256>>>(W0, U0, W1, U1, W2, U2);
    lstm3_fused<<<NBLK, NT, SMEM2>>>(x, b0, b1, b2, Wd, bd, out);
}